// round 14
// baseline (speedup 1.0000x reference)
#include <cuda_runtime.h>
#include <cstdint>

#define T_DIM  1024
#define KSZ    64
#define NSZ    64
#define TB     4                   // timesteps per CTA
#define ROWS   128                 // batch rows per CTA
#define PCH    16                  // rows per chunk
#define NCH    8                   // chunks (8*16 = 128)
#define NBUF   4
#define CSTR   260                 // chunk row stride in words (256 data + 4 pad)
#define CHW    (PCH * CSTR)        // 4160 words per chunk buffer
// smem (words): buffers [0, 4*CHW) ; sOut [4*CHW, 5*CHW) ; bias [5*CHW, +256)
// W staging (4*64*64 = 16384 words) overlays buffers region (16640 words)

__device__ __forceinline__ uint32_t f2tf32(float f) {
    uint32_t r; asm("cvt.rna.tf32.f32 %0, %1;" : "=r"(r) : "f"(f)); return r;
}
__device__ __forceinline__ uint32_t smem_u32(const void* p) {
    uint32_t a;
    asm("{ .reg .u64 t; cvta.to.shared.u64 t, %1; cvt.u32.u64 %0, t; }" : "=r"(a) : "l"(p));
    return a;
}
__device__ __forceinline__ void cp_async16(uint32_t dst, const void* src) {
    asm volatile("cp.async.cg.shared.global [%0], [%1], 16;" :: "r"(dst), "l"(src));
}

// one 16-row chunk: row = x[b, t0:t0+4, :] -> 1 KB contiguous; 1024 float4s
__device__ __forceinline__ void issue_chunk(float* dst, const float* __restrict__ x,
                                            int t0, int rowBase, int tid)
{
    #pragma unroll
    for (int i = 0; i < 4; i++) {
        int idx = tid + i * 256;          // float4 id 0..1023
        int r   = idx >> 6;               // row 0..15
        int c4  = idx & 63;               // float4 within 256-float row
        const float* src = x + ((size_t)(rowBase + r) * T_DIM + t0) * KSZ + c4 * 4;
        cp_async16(smem_u32(&dst[r * CSTR + c4 * 4]), src);
    }
    asm volatile("cp.async.commit_group;");
}

__global__ __launch_bounds__(256, 2)
void parallel_linear_wide(const float* __restrict__ x,
                          const float* __restrict__ W,
                          const float* __restrict__ bias,
                          float* __restrict__ out)
{
    extern __shared__ float smem[];
    float*    sBuf  = smem;                       // NBUF x CHW
    float*    sOut  = smem + NBUF * CHW;          // CHW
    float*    sBias = sOut + CHW;                 // 256
    uint32_t* sWst  = reinterpret_cast<uint32_t*>(smem);  // overlay: 4 x 4096 words

    const int bid = blockIdx.x;
    const int t0  = (bid >> 2) * TB;              // 4 CTAs share a t-group (W via L2)
    const int b0  = (bid & 3) * ROWS;

    const int tid  = threadIdx.x;
    const int warp = tid >> 5;
    const int lane = tid & 31;
    const int g    = lane >> 2;        // 0..7
    const int tg   = lane & 3;         // 0..3
    const int pair  = warp >> 1;       // 0..3 -> timestep t0+pair
    const int nhalf = warp & 1;        // 32-col half

    // ---- stage 4 W matrices -> tf32 into overlay region (before any cp.async) ----
    {
        const float4* Wg = reinterpret_cast<const float4*>(W + (size_t)t0 * (NSZ * KSZ));
        #pragma unroll
        for (int i = 0; i < 16; i++) {
            int idx = tid + i * 256;           // float4 id 0..4095 over 4 matrices
            float4 v = Wg[idx];
            uint4 u = make_uint4(f2tf32(v.x), f2tf32(v.y), f2tf32(v.z), f2tf32(v.w));
            *reinterpret_cast<uint4*>(&sWst[idx * 4]) = u;
        }
    }
    if (tid < TB * NSZ) sBias[tid] = bias[t0 * NSZ + tid];
    __syncthreads();

    // ---- W fragments ONCE into regs: 4 n-tiles x 8 ks x 2 = 64 regs (one-time LDS) ----
    uint32_t wf0[4][8], wf1[4][8];
    #pragma unroll
    for (int nt = 0; nt < 4; nt++) {
        const int ncol = nhalf * 32 + nt * 8 + g;
        #pragma unroll
        for (int ks = 0; ks < 8; ks++) {
            wf0[nt][ks] = sWst[pair * 4096 + ncol * 64 + ks * 8 + tg];
            wf1[nt][ks] = sWst[pair * 4096 + ncol * 64 + ks * 8 + tg + 4];
        }
    }
    float bb0[4], bb1[4];
    #pragma unroll
    for (int nt = 0; nt < 4; nt++) {
        bb0[nt] = sBias[pair * NSZ + nhalf * 32 + nt * 8 + 2 * tg];
        bb1[nt] = sBias[pair * NSZ + nhalf * 32 + nt * 8 + 2 * tg + 1];
    }
    __syncthreads();   // frags loaded; overlay region now reusable as pipeline buffers

    // ---- prologue: chunks 0,1,2 in flight ----
    issue_chunk(sBuf + 0 * CHW, x, t0, b0 + 0 * PCH, tid);
    issue_chunk(sBuf + 1 * CHW, x, t0, b0 + 1 * PCH, tid);
    issue_chunk(sBuf + 2 * CHW, x, t0, b0 + 2 * PCH, tid);

    // ---- fully unrolled 8-chunk pipeline ----
    #pragma unroll
    for (int c = 0; c < NCH; c++) {
        if      (c <= NCH - 4) asm volatile("cp.async.wait_group 2;");
        else if (c == NCH - 3) asm volatile("cp.async.wait_group 2;");
        else if (c == NCH - 2) asm volatile("cp.async.wait_group 1;");
        else                   asm volatile("cp.async.wait_group 0;");
        __syncthreads();   // chunk c visible; buffer c-1 free; sOut drained

        if (c + 3 < NCH)
            issue_chunk(sBuf + ((c + 3) & (NBUF - 1)) * CHW, x, t0,
                        b0 + (c + 3) * PCH, tid);

        const float* aP = sBuf + (c & (NBUF - 1)) * CHW + pair * 64;

        float acc[4][4];
        #pragma unroll
        for (int nt = 0; nt < 4; nt++)
            #pragma unroll
            for (int j = 0; j < 4; j++) acc[nt][j] = 0.f;

        #pragma unroll
        for (int ks = 0; ks < 8; ks++) {
            const int k0 = ks * 8;
            uint32_t a0 = f2tf32(aP[ g      * CSTR + k0 + tg]);
            uint32_t a1 = f2tf32(aP[(8 + g) * CSTR + k0 + tg]);
            uint32_t a2 = f2tf32(aP[ g      * CSTR + k0 + tg + 4]);
            uint32_t a3 = f2tf32(aP[(8 + g) * CSTR + k0 + tg + 4]);
            #pragma unroll
            for (int nt = 0; nt < 4; nt++) {
                asm volatile(
                    "mma.sync.aligned.m16n8k8.row.col.f32.tf32.tf32.f32 "
                    "{%0,%1,%2,%3}, {%4,%5,%6,%7}, {%8,%9}, {%0,%1,%2,%3};"
                    : "+f"(acc[nt][0]), "+f"(acc[nt][1]),
                      "+f"(acc[nt][2]), "+f"(acc[nt][3])
                    : "r"(a0), "r"(a1), "r"(a2), "r"(a3),
                      "r"(wf0[nt][ks]), "r"(wf1[nt][ks]));
            }
        }

        // ---- epilogue: +bias -> sOut bounce ----
        #pragma unroll
        for (int nt = 0; nt < 4; nt++) {
            const int col = pair * 64 + nhalf * 32 + nt * 8 + 2 * tg;
            *reinterpret_cast<float2*>(&sOut[ g      * CSTR + col]) =
                make_float2(acc[nt][0] + bb0[nt], acc[nt][1] + bb1[nt]);
            *reinterpret_cast<float2*>(&sOut[(8 + g) * CSTR + col]) =
                make_float2(acc[nt][2] + bb0[nt], acc[nt][3] + bb1[nt]);
        }
        __syncthreads();   // sOut complete

        // ---- cooperative write-out: 16 rows x 1 KB contiguous float4 bursts ----
        #pragma unroll
        for (int i = 0; i < 4; i++) {
            int idx = tid + i * 256;
            int r   = idx >> 6;
            int c4  = idx & 63;
            float4 v = *reinterpret_cast<const float4*>(&sOut[r * CSTR + c4 * 4]);
            *reinterpret_cast<float4*>(
                out + ((size_t)(b0 + c * PCH + r) * T_DIM + t0) * KSZ + c4 * 4) = v;
        }
    }
}

extern "C" void kernel_launch(void* const* d_in, const int* in_sizes, int n_in,
                              void* d_out, int out_size)
{
    const float* x = (const float*)d_in[0];
    const float* W = (const float*)d_in[1];
    const float* b = (const float*)d_in[2];
    float* out     = (float*)d_out;

    const int smem_bytes = (NBUF * CHW + CHW + TB * NSZ) * (int)sizeof(float); // 84224 B

    cudaFuncSetAttribute(parallel_linear_wide,
                         cudaFuncAttributeMaxDynamicSharedMemorySize, smem_bytes);

    parallel_linear_wide<<<(T_DIM / TB) * (512 / ROWS), 256, smem_bytes>>>(x, W, b, out);
}